// round 1
// baseline (speedup 1.0000x reference)
#include <cuda_runtime.h>

#define En 4096
#define Bn 8
#define HEADS 32
#define Dh 128

// Scratch: qkv[3][8][4096], o[8][4096]
__device__ float g_qkv[3 * Bn * En];
__device__ float g_o[Bn * En];

// Warp computes out[b][row0+r] = sum_e W[row0+r][e] * X[b][e], r=0..3, b=0..7.
// 32 accumulators per thread; butterfly transpose-reduce leaves one result per lane.
__device__ __forceinline__ void gemm_warp4(const float* __restrict__ W,
                                           const float* __restrict__ X,
                                           float* __restrict__ out,
                                           int row0, int lane) {
    const float4* __restrict__ W4 = reinterpret_cast<const float4*>(W);
    const float4* __restrict__ X4 = reinterpret_cast<const float4*>(X);

    float acc[32];
#pragma unroll
    for (int i = 0; i < 32; ++i) acc[i] = 0.f;

#pragma unroll 2
    for (int it = 0; it < 32; ++it) {
        int f4 = it * 32 + lane;  // float4 index into a 4096-float row
        float4 w0 = __ldcs(W4 + (size_t)(row0 + 0) * 1024 + f4);
        float4 w1 = __ldcs(W4 + (size_t)(row0 + 1) * 1024 + f4);
        float4 w2 = __ldcs(W4 + (size_t)(row0 + 2) * 1024 + f4);
        float4 w3 = __ldcs(W4 + (size_t)(row0 + 3) * 1024 + f4);
#pragma unroll
        for (int b = 0; b < 8; ++b) {
            float4 xv = __ldg(X4 + b * 1024 + f4);
            acc[0 * 8 + b] += w0.x * xv.x + w0.y * xv.y + w0.z * xv.z + w0.w * xv.w;
            acc[1 * 8 + b] += w1.x * xv.x + w1.y * xv.y + w1.z * xv.z + w1.w * xv.w;
            acc[2 * 8 + b] += w2.x * xv.x + w2.y * xv.y + w2.z * xv.z + w2.w * xv.w;
            acc[3 * 8 + b] += w3.x * xv.x + w3.y * xv.y + w3.z * xv.z + w3.w * xv.w;
        }
    }

    // Butterfly transpose-reduce: 31 shfl+add total. After 5 steps, lane L
    // holds the full sum of value index j = bitreverse5(L).
    int n = 32;
#pragma unroll
    for (int m = 1; m <= 16; m <<= 1) {
        n >>= 1;
        bool up = (lane & m) != 0;
#pragma unroll
        for (int i = 0; i < n; ++i) {
            float keep = up ? acc[i + n] : acc[i];
            float send = up ? acc[i] : acc[i + n];
            keep += __shfl_xor_sync(0xffffffffu, send, m);
            acc[i] = keep;
        }
    }
    int j = ((lane & 1) << 4) | ((lane & 2) << 2) | (lane & 4) |
            ((lane >> 2) & 2) | ((lane >> 4) & 1);
    int r = j >> 3;
    int b = j & 7;
    out[b * En + row0 + r] = acc[0];
}

// grid (128, 3), block 256: blockIdx.y selects projection; 8 warps x 4 rows = 32 rows/block
__global__ void __launch_bounds__(256, 2)
qkv_kernel(const float* __restrict__ Wq, const float* __restrict__ Wk,
           const float* __restrict__ Wv, const float* __restrict__ x) {
    int warp = threadIdx.x >> 5;
    int lane = threadIdx.x & 31;
    int row0 = (blockIdx.x * 8 + warp) * 4;
    const float* W = (blockIdx.y == 0) ? Wq : ((blockIdx.y == 1) ? Wk : Wv);
    gemm_warp4(W, x, g_qkv + blockIdx.y * (Bn * En), row0, lane);
}

// Attention with all-ones KV cache collapses to o[d] = c1 + c2 * v[d] per (b,h).
// One warp per (b,h) pair: 256 warps total.
__global__ void __launch_bounds__(256)
attn_kernel() {
    int gtid = blockIdx.x * blockDim.x + threadIdx.x;
    int warp = gtid >> 5;   // 0..255
    int lane = gtid & 31;
    int b = warp >> 5;      // 0..7
    int h = warp & 31;      // 0..31

    const float4* q4 = reinterpret_cast<const float4*>(g_qkv + (0 * Bn + b) * En + h * Dh);
    const float4* k4 = reinterpret_cast<const float4*>(g_qkv + (1 * Bn + b) * En + h * Dh);
    const float4* v4 = reinterpret_cast<const float4*>(g_qkv + (2 * Bn + b) * En + h * Dh);

    float4 qv = q4[lane];
    float4 kv = k4[lane];
    float4 vv = v4[lane];

    float sq = qv.x + qv.y + qv.z + qv.w;
    float dp = qv.x * kv.x + qv.y * kv.y + qv.z * kv.z + qv.w * kv.w;
#pragma unroll
    for (int m = 16; m >= 1; m >>= 1) {
        sq += __shfl_xor_sync(0xffffffffu, sq, m);
        dp += __shfl_xor_sync(0xffffffffu, dp, m);
    }

    const float scale = 0.08838834764831845f;  // 1/sqrt(128)
    float s0 = sq * scale;                      // score vs every all-ones cache row
    float sL = dp * scale;                      // score vs appended k
    float mx = fmaxf(s0, sL);
    float e0 = expf(s0 - mx);
    float eL = expf(sL - mx);
    float inv = 1.0f / (4095.0f * e0 + eL);
    float c1 = 4095.0f * e0 * inv;              // total weight on ones-vectors
    float c2 = eL * inv;                        // weight on v

    float4* o4 = reinterpret_cast<float4*>(g_o + b * En + h * Dh);
    o4[lane] = make_float4(c1 + c2 * vv.x, c1 + c2 * vv.y,
                           c1 + c2 * vv.z, c1 + c2 * vv.w);
}

// grid 128, block 256: out[b][e] = sum_f o[b][f] * Wo[e][f]
__global__ void __launch_bounds__(256, 2)
oproj_kernel(const float* __restrict__ Wo, float* __restrict__ out) {
    int warp = threadIdx.x >> 5;
    int lane = threadIdx.x & 31;
    int row0 = (blockIdx.x * 8 + warp) * 4;
    gemm_warp4(Wo, g_o, out, row0, lane);
}

extern "C" void kernel_launch(void* const* d_in, const int* in_sizes, int n_in,
                              void* d_out, int out_size) {
    const float* x  = (const float*)d_in[0];
    const float* Wq = (const float*)d_in[1];
    const float* Wk = (const float*)d_in[2];
    const float* Wv = (const float*)d_in[3];
    const float* Wo = (const float*)d_in[4];
    float* out = (float*)d_out;

    dim3 gq(128, 3);
    qkv_kernel<<<gq, 256>>>(Wq, Wk, Wv, x);
    attn_kernel<<<32, 256>>>();
    oproj_kernel<<<128, 256>>>(Wo, out);
}